// round 1
// baseline (speedup 1.0000x reference)
#include <cuda_runtime.h>

#define NMAX 100000
#define EMAX 1600000
#define HID 64

// ---------------- scratch (device globals: allocation-free rule) ----------------
__device__ int   g_deg[NMAX];
__device__ int   g_rowptr[NMAX + 1];
__device__ int   g_cursor[NMAX];
__device__ int   g_col[EMAX];
__device__ float g_norm[NMAX];
__device__ float g_bufA[(size_t)NMAX * HID];
__device__ float g_bufB[(size_t)NMAX * HID];
__device__ float4 g_pq[NMAX];

// ---------------- CSR build ----------------
__global__ void zero_deg_kernel(int n) {
    int i = blockIdx.x * blockDim.x + threadIdx.x;
    if (i < n) g_deg[i] = 0;
}

__global__ void hist_kernel(const int* __restrict__ dst, int e) {
    int i = blockIdx.x * blockDim.x + threadIdx.x;
    if (i < e) atomicAdd(&g_deg[dst[i]], 1);
}

// single-block exclusive scan (n up to NMAX), also seeds cursor = rowptr
__global__ void scan_kernel(int n) {
    __shared__ int sums[1024];
    int t = threadIdx.x;
    int chunk = (n + 1023) >> 10;
    int lo = t * chunk;
    int hi = lo + chunk; if (hi > n) hi = n;
    int s = 0;
    for (int i = lo; i < hi; i++) s += g_deg[i];
    sums[t] = s;
    __syncthreads();
    // Hillis-Steele inclusive scan
    for (int off = 1; off < 1024; off <<= 1) {
        int v = (t >= off) ? sums[t - off] : 0;
        __syncthreads();
        sums[t] += v;
        __syncthreads();
    }
    int run = (t == 0) ? 0 : sums[t - 1];
    for (int i = lo; i < hi; i++) {
        g_rowptr[i] = run;
        g_cursor[i] = run;
        run += g_deg[i];
    }
    if (hi == n) g_rowptr[n] = run;  // total == E (tail threads write same value)
}

__global__ void scatter_kernel(const int* __restrict__ src,
                               const int* __restrict__ dst, int e) {
    int i = blockIdx.x * blockDim.x + threadIdx.x;
    if (i < e) {
        int p = atomicAdd(&g_cursor[dst[i]], 1);
        g_col[p] = src[i];
    }
}

// ---------------- norm: 1 / |distinct({src : dst=i} ∪ {i})| ----------------
__global__ void norm_kernel(int n) {
    int i = blockIdx.x * blockDim.x + threadIdx.x;
    if (i >= n) return;
    int lo = g_rowptr[i], hi = g_rowptr[i + 1];
    int cache[64];
    int m = 0;
    int cnt = 1;  // diagonal always present
    for (int j = lo; j < hi; j++) {
        int s = g_col[j];
        if (s == i) continue;  // merges with diagonal
        bool dup = false;
        for (int k = 0; k < m; k++)
            if (cache[k] == s) { dup = true; break; }
        if (dup) continue;
        if (m < 64) {
            cache[m++] = s;
            cnt++;
        } else {
            // overflow fallback (degree > 64 is ~impossible for Poisson(16), but exact)
            bool d2 = false;
            for (int jj = lo; jj < j; jj++)
                if (g_col[jj] == s) { d2 = true; break; }
            if (!d2) cnt++;
        }
    }
    g_norm[i] = 1.0f / (float)cnt;
}

// ---------------- dense linear: out[n,64] = x[n,K] @ W[K,64] + b ----------------
template <int K>
__global__ __launch_bounds__(256) void lin_kernel(const float* __restrict__ x,
                                                  const float* __restrict__ W,
                                                  const float* __restrict__ b,
                                                  float* __restrict__ out, int n) {
    __shared__ float Ws[K * HID];
    __shared__ float bs[HID];
    for (int i = threadIdx.x; i < (K * HID) / 4; i += blockDim.x)
        ((float4*)Ws)[i] = ((const float4*)W)[i];
    if (threadIdx.x < HID) bs[threadIdx.x] = b[threadIdx.x];
    __syncthreads();

    int row = blockIdx.x * blockDim.x + threadIdx.x;
    if (row >= n) return;

    float acc[HID];
#pragma unroll
    for (int c = 0; c < HID; c++) acc[c] = 0.f;

    const float4* xr = (const float4*)(x + (size_t)row * K);
#pragma unroll
    for (int k4 = 0; k4 < K / 4; k4++) {
        float4 xv = xr[k4];
        float xk[4] = {xv.x, xv.y, xv.z, xv.w};
#pragma unroll
        for (int kk = 0; kk < 4; kk++) {
            float xs = xk[kk];
            const float4* wr = (const float4*)(Ws + (k4 * 4 + kk) * HID);
#pragma unroll
            for (int c = 0; c < HID / 4; c++) {
                float4 w = wr[c];  // uniform address across warp -> LDS broadcast
                acc[4 * c + 0] += xs * w.x;
                acc[4 * c + 1] += xs * w.y;
                acc[4 * c + 2] += xs * w.z;
                acc[4 * c + 3] += xs * w.w;
            }
        }
    }

    float4* o = (float4*)(out + (size_t)row * HID);
#pragma unroll
    for (int c = 0; c < HID / 4; c++) {
        float4 v;
        v.x = acc[4 * c + 0] + bs[4 * c + 0];
        v.y = acc[4 * c + 1] + bs[4 * c + 1];
        v.z = acc[4 * c + 2] + bs[4 * c + 2];
        v.w = acc[4 * c + 3] + bs[4 * c + 3];
        o[c] = v;
    }
}

// ---------------- aggregation + combine: warp per node ----------------
// out[i] = norm[i] * (w0*h[i] + w0*w1 * sum_{src in CSR row i} h[src]) [, relu]
__global__ void agg_kernel(const float* __restrict__ h,
                           const float* __restrict__ wpan,
                           float* __restrict__ out, int n, int relu) {
    int wid = (blockIdx.x * blockDim.x + threadIdx.x) >> 5;
    int lane = threadIdx.x & 31;
    if (wid >= n) return;
    int lo = g_rowptr[wid], hi = g_rowptr[wid + 1];
    const float2* h2 = (const float2*)h;
    float ax = 0.f, ay = 0.f;
    int j = lo;
    for (; j + 1 < hi; j += 2) {  // unroll 2 for MLP
        int s0 = g_col[j];
        int s1 = g_col[j + 1];
        float2 v0 = h2[(size_t)s0 * 32 + lane];
        float2 v1 = h2[(size_t)s1 * 32 + lane];
        ax += v0.x; ay += v0.y;
        ax += v1.x; ay += v1.y;
    }
    if (j < hi) {
        int s0 = g_col[j];
        float2 v0 = h2[(size_t)s0 * 32 + lane];
        ax += v0.x; ay += v0.y;
    }
    float w0 = wpan[0];
    float w01 = w0 * wpan[1];
    float nm = g_norm[wid];
    float2 hv = h2[(size_t)wid * 32 + lane];
    float ox = nm * (w0 * hv.x + w01 * ax);
    float oy = nm * (w0 * hv.y + w01 * ay);
    if (relu) { ox = fmaxf(ox, 0.f); oy = fmaxf(oy, 0.f); }
    ((float2*)out)[(size_t)wid * 32 + lane] = make_float2(ox, oy);
}

// ---------------- per-node classifier halves: pq[i] = (h[i]@wc_top, h[i]@wc_bot) ----------------
__global__ void pq_kernel(const float* __restrict__ h,
                          const float* __restrict__ wc, int n) {
    __shared__ float wcs[256];  // wc is [128,2]
    for (int i = threadIdx.x; i < 256; i += blockDim.x) wcs[i] = wc[i];
    __syncthreads();
    int i = blockIdx.x * blockDim.x + threadIdx.x;
    if (i >= n) return;
    float p0 = 0.f, p1 = 0.f, q0 = 0.f, q1 = 0.f;
    const float4* hr = (const float4*)(h + (size_t)i * HID);
#pragma unroll
    for (int k4 = 0; k4 < 16; k4++) {
        float4 hv = hr[k4];
        float hk[4] = {hv.x, hv.y, hv.z, hv.w};
#pragma unroll
        for (int t = 0; t < 4; t++) {
            int k = 4 * k4 + t;
            p0 += hk[t] * wcs[2 * k + 0];
            p1 += hk[t] * wcs[2 * k + 1];
            q0 += hk[t] * wcs[128 + 2 * k + 0];
            q1 += hk[t] * wcs[128 + 2 * k + 1];
        }
    }
    g_pq[i] = make_float4(p0, p1, q0, q1);
}

// ---------------- per-edge output: out[e] = p[src] + q[dst] + bc ----------------
__global__ void edge_kernel(const int* __restrict__ src,
                            const int* __restrict__ dst,
                            const float* __restrict__ bc,
                            float* __restrict__ out, int e) {
    int i = blockIdx.x * blockDim.x + threadIdx.x;
    if (i >= e) return;
    int s = src[i];
    int d = dst[i];
    float4 ps = g_pq[s];
    float4 qd = g_pq[d];
    float b0 = bc[0], b1 = bc[1];
    ((float2*)out)[i] = make_float2(ps.x + qd.z + b0, ps.y + qd.w + b1);
}

// ---------------- launch ----------------
extern "C" void kernel_launch(void* const* d_in, const int* in_sizes, int n_in,
                              void* d_out, int out_size) {
    const float* x   = (const float*)d_in[0];
    const int*   ei  = (const int*)d_in[1];
    const float* w1  = (const float*)d_in[2];
    const float* b1  = (const float*)d_in[3];
    const float* p1  = (const float*)d_in[4];  // w1_pan
    const float* w2  = (const float*)d_in[5];
    const float* b2  = (const float*)d_in[6];
    const float* p2  = (const float*)d_in[7];  // w2_pan
    const float* wc  = (const float*)d_in[8];
    const float* bc  = (const float*)d_in[9];
    float* out = (float*)d_out;

    int n = in_sizes[0] / 128;
    int e = in_sizes[1] / 2;
    const int* src = ei;
    const int* dst = ei + e;

    float* bufA = nullptr;
    float* bufB = nullptr;
    cudaGetSymbolAddress((void**)&bufA, g_bufA);
    cudaGetSymbolAddress((void**)&bufB, g_bufB);

    int nb256 = (n + 255) / 256;
    int eb256 = (e + 255) / 256;

    // graph structure (recomputed deterministically every call)
    zero_deg_kernel<<<nb256, 256>>>(n);
    hist_kernel<<<eb256, 256>>>(dst, e);
    scan_kernel<<<1, 1024>>>(n);
    scatter_kernel<<<eb256, 256>>>(src, dst, e);
    norm_kernel<<<nb256, 256>>>(n);

    // layer 1
    lin_kernel<128><<<nb256, 256>>>(x, w1, b1, bufA, n);
    agg_kernel<<<(n * 32 + 255) / 256, 256>>>(bufA, p1, bufB, n, 1);

    // layer 2
    lin_kernel<64><<<nb256, 256>>>(bufB, w2, b2, bufA, n);
    agg_kernel<<<(n * 32 + 255) / 256, 256>>>(bufA, p2, bufB, n, 0);

    // edge classifier
    pq_kernel<<<nb256, 256>>>(bufB, wc, n);
    edge_kernel<<<eb256, 256>>>(src, dst, bc, out, e);
}

// round 2
// speedup vs baseline: 1.4523x; 1.4523x over previous
#include <cuda_runtime.h>

#define NMAX 100000
#define EMAX 1600000
#define HID 64
#define HASH_BITS 22
#define HASH_SIZE (1u << HASH_BITS)
#define HASH_MASK (HASH_SIZE - 1u)
#define HEMPTY 0xFFFFFFFFFFFFFFFFull

// ---------------- scratch (device globals: allocation-free rule) ----------------
__device__ int   g_deg[NMAX];
__device__ int   g_cnt[NMAX];          // distinct in-neighbor count (excl. diagonal)
__device__ int   g_rowptr[NMAX + 1];
__device__ int   g_cursor[NMAX];
__device__ int   g_bsum[1024];         // block sums for multi-block scan
__device__ int   g_col[EMAX];
__device__ float g_norm[NMAX];
__device__ unsigned long long g_hash[HASH_SIZE];
__device__ float g_bufA[(size_t)NMAX * HID];
__device__ float g_bufB[(size_t)NMAX * HID];
__device__ float4 g_pq[NMAX];

// ---------------- init: zero deg/cnt, clear hash ----------------
__global__ void init_kernel(int n) {
    int i = blockIdx.x * blockDim.x + threadIdx.x;
    if (i < n) { g_deg[i] = 0; g_cnt[i] = 0; }
    // clear hash table (grid sized to cover max(n, HASH_SIZE))
    for (unsigned j = blockIdx.x * blockDim.x + threadIdx.x;
         j < HASH_SIZE; j += gridDim.x * blockDim.x)
        g_hash[j] = HEMPTY;
}

// ---------------- histogram (CSR degrees, with multiplicity) + distinct count (hash) ----------------
__global__ void hist_distinct_kernel(const int* __restrict__ src,
                                     const int* __restrict__ dst, int e) {
    int i = blockIdx.x * blockDim.x + threadIdx.x;
    if (i >= e) return;
    int s = src[i];
    int d = dst[i];
    atomicAdd(&g_deg[d], 1);
    if (s == d) return;  // merges with diagonal in coalesce
    unsigned long long key = ((unsigned long long)(unsigned)d << 32) | (unsigned)s;
    unsigned h = (unsigned)((key * 0x9E3779B97F4A7C15ull) >> (64 - HASH_BITS));
    for (;;) {
        unsigned long long old = atomicCAS(&g_hash[h], HEMPTY, key);
        if (old == HEMPTY) { atomicAdd(&g_cnt[d], 1); return; }
        if (old == key) return;
        h = (h + 1) & HASH_MASK;
    }
}

// ---------------- multi-block exclusive scan of g_deg -> g_rowptr ----------------
// pass 1: per-block inclusive scan; write per-element exclusive (block-local) + block sums
__global__ void scan1_kernel(int n) {
    __shared__ int sh[1024];
    int t = threadIdx.x;
    int i = blockIdx.x * 1024 + t;
    int v = (i < n) ? g_deg[i] : 0;
    sh[t] = v;
    __syncthreads();
    for (int off = 1; off < 1024; off <<= 1) {
        int u = (t >= off) ? sh[t - off] : 0;
        __syncthreads();
        sh[t] += u;
        __syncthreads();
    }
    if (i < n) g_rowptr[i] = sh[t] - v;            // block-local exclusive
    if (t == 1023) g_bsum[blockIdx.x] = sh[1023];  // block total
}

// pass 2: scan block sums (nb <= 1024) in one block; writes exclusive sums in place,
// and total edge count into g_rowptr[n]
__global__ void scan2_kernel(int nb, int n) {
    __shared__ int sh[1024];
    int t = threadIdx.x;
    int v = (t < nb) ? g_bsum[t] : 0;
    sh[t] = v;
    __syncthreads();
    for (int off = 1; off < 1024; off <<= 1) {
        int u = (t >= off) ? sh[t - off] : 0;
        __syncthreads();
        sh[t] += u;
        __syncthreads();
    }
    if (t < nb) g_bsum[t] = sh[t] - v;  // exclusive
    if (t == 1023) g_rowptr[n] = sh[1023];
}

// pass 3: add block offsets, seed cursor, and finalize norm
__global__ void scan3_kernel(int n) {
    int i = blockIdx.x * 1024 + threadIdx.x;
    if (i >= n) return;
    int r = g_rowptr[i] + g_bsum[blockIdx.x];
    g_rowptr[i] = r;
    g_cursor[i] = r;
    g_norm[i] = 1.0f / (float)(1 + g_cnt[i]);
}

// ---------------- CSR scatter ----------------
__global__ void scatter_kernel(const int* __restrict__ src,
                               const int* __restrict__ dst, int e) {
    int i = blockIdx.x * blockDim.x + threadIdx.x;
    if (i < e) {
        int p = atomicAdd(&g_cursor[dst[i]], 1);
        g_col[p] = src[i];
    }
}

// ---------------- dense linear: out[n,64] = x[n,K] @ W[K,64] + b ----------------
template <int K>
__global__ __launch_bounds__(256) void lin_kernel(const float* __restrict__ x,
                                                  const float* __restrict__ W,
                                                  const float* __restrict__ b,
                                                  float* __restrict__ out, int n) {
    __shared__ float Ws[K * HID];
    __shared__ float bs[HID];
    for (int i = threadIdx.x; i < (K * HID) / 4; i += blockDim.x)
        ((float4*)Ws)[i] = ((const float4*)W)[i];
    if (threadIdx.x < HID) bs[threadIdx.x] = b[threadIdx.x];
    __syncthreads();

    int row = blockIdx.x * blockDim.x + threadIdx.x;
    if (row >= n) return;

    float acc[HID];
#pragma unroll
    for (int c = 0; c < HID; c++) acc[c] = 0.f;

    const float4* xr = (const float4*)(x + (size_t)row * K);
#pragma unroll
    for (int k4 = 0; k4 < K / 4; k4++) {
        float4 xv = xr[k4];
        float xk[4] = {xv.x, xv.y, xv.z, xv.w};
#pragma unroll
        for (int kk = 0; kk < 4; kk++) {
            float xs = xk[kk];
            const float4* wr = (const float4*)(Ws + (k4 * 4 + kk) * HID);
#pragma unroll
            for (int c = 0; c < HID / 4; c++) {
                float4 w = wr[c];  // uniform address across warp -> LDS broadcast
                acc[4 * c + 0] += xs * w.x;
                acc[4 * c + 1] += xs * w.y;
                acc[4 * c + 2] += xs * w.z;
                acc[4 * c + 3] += xs * w.w;
            }
        }
    }

    float4* o = (float4*)(out + (size_t)row * HID);
#pragma unroll
    for (int c = 0; c < HID / 4; c++) {
        float4 v;
        v.x = acc[4 * c + 0] + bs[4 * c + 0];
        v.y = acc[4 * c + 1] + bs[4 * c + 1];
        v.z = acc[4 * c + 2] + bs[4 * c + 2];
        v.w = acc[4 * c + 3] + bs[4 * c + 3];
        o[c] = v;
    }
}

// ---------------- aggregation + combine: warp per node ----------------
// out[i] = norm[i] * (w0*h[i] + w0*w1 * sum_{src in CSR row i} h[src]) [, relu]
__global__ void agg_kernel(const float* __restrict__ h,
                           const float* __restrict__ wpan,
                           float* __restrict__ out, int n, int relu) {
    int wid = (blockIdx.x * blockDim.x + threadIdx.x) >> 5;
    int lane = threadIdx.x & 31;
    if (wid >= n) return;
    int lo = g_rowptr[wid], hi = g_rowptr[wid + 1];
    const float2* h2 = (const float2*)h;
    float ax = 0.f, ay = 0.f;
    int j = lo;
    for (; j + 1 < hi; j += 2) {  // unroll 2 for MLP
        int s0 = g_col[j];
        int s1 = g_col[j + 1];
        float2 v0 = h2[(size_t)s0 * 32 + lane];
        float2 v1 = h2[(size_t)s1 * 32 + lane];
        ax += v0.x; ay += v0.y;
        ax += v1.x; ay += v1.y;
    }
    if (j < hi) {
        int s0 = g_col[j];
        float2 v0 = h2[(size_t)s0 * 32 + lane];
        ax += v0.x; ay += v0.y;
    }
    float w0 = wpan[0];
    float w01 = w0 * wpan[1];
    float nm = g_norm[wid];
    float2 hv = h2[(size_t)wid * 32 + lane];
    float ox = nm * (w0 * hv.x + w01 * ax);
    float oy = nm * (w0 * hv.y + w01 * ay);
    if (relu) { ox = fmaxf(ox, 0.f); oy = fmaxf(oy, 0.f); }
    ((float2*)out)[(size_t)wid * 32 + lane] = make_float2(ox, oy);
}

// ---------------- per-node classifier halves ----------------
__global__ void pq_kernel(const float* __restrict__ h,
                          const float* __restrict__ wc, int n) {
    __shared__ float wcs[256];  // wc is [128,2]
    for (int i = threadIdx.x; i < 256; i += blockDim.x) wcs[i] = wc[i];
    __syncthreads();
    int i = blockIdx.x * blockDim.x + threadIdx.x;
    if (i >= n) return;
    float p0 = 0.f, p1 = 0.f, q0 = 0.f, q1 = 0.f;
    const float4* hr = (const float4*)(h + (size_t)i * HID);
#pragma unroll
    for (int k4 = 0; k4 < 16; k4++) {
        float4 hv = hr[k4];
        float hk[4] = {hv.x, hv.y, hv.z, hv.w};
#pragma unroll
        for (int t = 0; t < 4; t++) {
            int k = 4 * k4 + t;
            p0 += hk[t] * wcs[2 * k + 0];
            p1 += hk[t] * wcs[2 * k + 1];
            q0 += hk[t] * wcs[128 + 2 * k + 0];
            q1 += hk[t] * wcs[128 + 2 * k + 1];
        }
    }
    g_pq[i] = make_float4(p0, p1, q0, q1);
}

// ---------------- per-edge output ----------------
__global__ void edge_kernel(const int* __restrict__ src,
                            const int* __restrict__ dst,
                            const float* __restrict__ bc,
                            float* __restrict__ out, int e) {
    int i = blockIdx.x * blockDim.x + threadIdx.x;
    if (i >= e) return;
    int s = src[i];
    int d = dst[i];
    float4 ps = g_pq[s];
    float4 qd = g_pq[d];
    float b0 = bc[0], b1 = bc[1];
    ((float2*)out)[i] = make_float2(ps.x + qd.z + b0, ps.y + qd.w + b1);
}

// ---------------- launch ----------------
extern "C" void kernel_launch(void* const* d_in, const int* in_sizes, int n_in,
                              void* d_out, int out_size) {
    const float* x   = (const float*)d_in[0];
    const int*   ei  = (const int*)d_in[1];
    const float* w1  = (const float*)d_in[2];
    const float* b1  = (const float*)d_in[3];
    const float* p1  = (const float*)d_in[4];  // w1_pan
    const float* w2  = (const float*)d_in[5];
    const float* b2  = (const float*)d_in[6];
    const float* p2  = (const float*)d_in[7];  // w2_pan
    const float* wc  = (const float*)d_in[8];
    const float* bc  = (const float*)d_in[9];
    float* out = (float*)d_out;

    int n = in_sizes[0] / 128;
    int e = in_sizes[1] / 2;
    const int* src = ei;
    const int* dst = ei + e;

    float* bufA = nullptr;
    float* bufB = nullptr;
    cudaGetSymbolAddress((void**)&bufA, g_bufA);
    cudaGetSymbolAddress((void**)&bufB, g_bufB);

    int nb256 = (n + 255) / 256;
    int eb256 = (e + 255) / 256;
    int nb1024 = (n + 1023) / 1024;

    // graph structure (recomputed deterministically every call)
    init_kernel<<<4096, 1024>>>(n);                       // zero deg/cnt, clear hash
    hist_distinct_kernel<<<eb256, 256>>>(src, dst, e);    // CSR degrees + distinct counts
    scan1_kernel<<<nb1024, 1024>>>(n);
    scan2_kernel<<<1, 1024>>>(nb1024, n);
    scan3_kernel<<<nb1024, 1024>>>(n);                    // offsets + cursor + norm
    scatter_kernel<<<eb256, 256>>>(src, dst, e);

    // layer 1
    lin_kernel<128><<<nb256, 256>>>(x, w1, b1, bufA, n);
    agg_kernel<<<(n * 32 + 255) / 256, 256>>>(bufA, p1, bufB, n, 1);

    // layer 2
    lin_kernel<64><<<nb256, 256>>>(bufB, w2, b2, bufA, n);
    agg_kernel<<<(n * 32 + 255) / 256, 256>>>(bufA, p2, bufB, n, 0);

    // edge classifier
    pq_kernel<<<nb256, 256>>>(bufB, wc, n);
    edge_kernel<<<eb256, 256>>>(src, dst, bc, out, e);
}

// round 3
// speedup vs baseline: 1.4795x; 1.0187x over previous
#include <cuda_runtime.h>

#define NMAX 100000
#define EMAX 1600000
#define HID 64
#define HASH_BITS 22
#define HASH_SIZE (1u << HASH_BITS)
#define HASH_MASK (HASH_SIZE - 1u)
#define HEMPTY 0xFFFFFFFFFFFFFFFFull

// ---------------- scratch (device globals: allocation-free rule) ----------------
__device__ int   g_deg[NMAX];
__device__ int   g_cnt[NMAX];          // distinct in-neighbor count (excl. diagonal)
__device__ int   g_rowptr[NMAX + 1];
__device__ int   g_cursor[NMAX];
__device__ int   g_bsum[1024];         // block sums for multi-block scan
__device__ int   g_col[EMAX];
__device__ float g_norm[NMAX];
__device__ unsigned long long g_hash[HASH_SIZE];
__device__ float g_bufA[(size_t)NMAX * HID];
__device__ float g_bufB[(size_t)NMAX * HID];
__device__ float4 g_pq[NMAX];

// ---------------- init: zero deg/cnt, clear hash (vectorized) ----------------
__global__ void init_kernel(int n) {
    int gtid = blockIdx.x * blockDim.x + threadIdx.x;
    int stride = gridDim.x * blockDim.x;
    for (int i = gtid; i < n; i += stride) { g_deg[i] = 0; g_cnt[i] = 0; }
    ulonglong2* h2 = (ulonglong2*)g_hash;
    ulonglong2 ev; ev.x = HEMPTY; ev.y = HEMPTY;
    for (unsigned j = gtid; j < HASH_SIZE / 2; j += stride) h2[j] = ev;
}

// ---------------- FUSED: lin1 (half-row per thread) + hist/distinct ----------------
// blocks [0, nbLin): out[n,64] = x[n,128] @ W + b, 2 threads per row (32 cols each)
// blocks [nbLin, ...): histogram of dst + hash-based distinct (src,dst) counting, 4 edges/thread
__global__ __launch_bounds__(256) void fused_lin1_hist_kernel(
    const float* __restrict__ x, const float* __restrict__ W,
    const float* __restrict__ b,
    const int* __restrict__ src, const int* __restrict__ dst,
    float* __restrict__ out, int n, int e, int nbLin)
{
    __shared__ float Ws[128 * HID];   // 32 KB
    __shared__ float bs[HID];

    if (blockIdx.x < nbLin) {
        // -------- GEMM branch --------
        for (int i = threadIdx.x; i < (128 * HID) / 4; i += 256)
            ((float4*)Ws)[i] = ((const float4*)W)[i];
        if (threadIdx.x < HID) bs[threadIdx.x] = b[threadIdx.x];
        __syncthreads();

        int gid = blockIdx.x * 256 + threadIdx.x;
        int row = gid >> 1;
        int half = gid & 1;           // which 32-column half
        if (row >= n) return;

        float acc[32];
#pragma unroll
        for (int c = 0; c < 32; c++) acc[c] = 0.f;

        const float4* xr = (const float4*)(x + (size_t)row * 128);
        int cbase = half * 32;
#pragma unroll
        for (int k4 = 0; k4 < 32; k4++) {
            float4 xv = xr[k4];
            float xk[4] = {xv.x, xv.y, xv.z, xv.w};
#pragma unroll
            for (int kk = 0; kk < 4; kk++) {
                float xs = xk[kk];
                const float4* wr = (const float4*)(Ws + (k4 * 4 + kk) * HID + cbase);
#pragma unroll
                for (int c = 0; c < 8; c++) {
                    float4 w = wr[c];
                    acc[4 * c + 0] += xs * w.x;
                    acc[4 * c + 1] += xs * w.y;
                    acc[4 * c + 2] += xs * w.z;
                    acc[4 * c + 3] += xs * w.w;
                }
            }
        }
        float4* o = (float4*)(out + (size_t)row * HID + cbase);
#pragma unroll
        for (int c = 0; c < 8; c++) {
            float4 v;
            v.x = acc[4 * c + 0] + bs[cbase + 4 * c + 0];
            v.y = acc[4 * c + 1] + bs[cbase + 4 * c + 1];
            v.z = acc[4 * c + 2] + bs[cbase + 4 * c + 2];
            v.w = acc[4 * c + 3] + bs[cbase + 4 * c + 3];
            o[c] = v;
        }
    } else {
        // -------- histogram + distinct branch, 4 edges per thread --------
        int bid = blockIdx.x - nbLin;
        int i0 = (bid * 256 + threadIdx.x) * 4;
        if (i0 >= e) return;
        int ss[4], dd[4];
        int cnt;
        if (i0 + 4 <= e) {
            int4 s4 = *(const int4*)(src + i0);
            int4 d4 = *(const int4*)(dst + i0);
            ss[0] = s4.x; ss[1] = s4.y; ss[2] = s4.z; ss[3] = s4.w;
            dd[0] = d4.x; dd[1] = d4.y; dd[2] = d4.z; dd[3] = d4.w;
            cnt = 4;
        } else {
            cnt = e - i0;
            for (int t = 0; t < cnt; t++) { ss[t] = src[i0 + t]; dd[t] = dst[i0 + t]; }
        }
        for (int t = 0; t < cnt; t++) {
            int s = ss[t], d = dd[t];
            atomicAdd(&g_deg[d], 1);
            if (s == d) continue;  // merges with diagonal in coalesce
            unsigned long long key =
                ((unsigned long long)(unsigned)d << 32) | (unsigned)s;
            unsigned h = (unsigned)((key * 0x9E3779B97F4A7C15ull) >> (64 - HASH_BITS));
            for (;;) {
                unsigned long long old = atomicCAS(&g_hash[h], HEMPTY, key);
                if (old == HEMPTY) { atomicAdd(&g_cnt[d], 1); break; }
                if (old == key) break;
                h = (h + 1) & HASH_MASK;
            }
        }
    }
}

// ---------------- scan pass 1: per-block exclusive + block sums ----------------
__global__ void scan1_kernel(int n) {
    __shared__ int sh[1024];
    int t = threadIdx.x;
    int i = blockIdx.x * 1024 + t;
    int v = (i < n) ? g_deg[i] : 0;
    sh[t] = v;
    __syncthreads();
    for (int off = 1; off < 1024; off <<= 1) {
        int u = (t >= off) ? sh[t - off] : 0;
        __syncthreads();
        sh[t] += u;
        __syncthreads();
    }
    if (i < n) g_rowptr[i] = sh[t] - v;            // block-local exclusive
    if (t == 1023) g_bsum[blockIdx.x] = sh[1023];  // block total
}

// ---------------- scan pass 2 (fused): inline block-sum prefix + cursor + norm ----------------
__global__ void scan3_kernel(int n, int nb) {
    __shared__ int shp[128], sht[128];
    int t = threadIdx.x;
    if (t < 128) {
        int vp = 0, vt = 0;
        if (t < nb) {
            int bsv = g_bsum[t];
            vt = bsv;
            if (t < (int)blockIdx.x) vp = bsv;
        }
        shp[t] = vp; sht[t] = vt;
    }
    __syncthreads();
    for (int off = 64; off > 0; off >>= 1) {
        if (t < off) { shp[t] += shp[t + off]; sht[t] += sht[t + off]; }
        __syncthreads();
    }
    int prefix = shp[0];

    int i = blockIdx.x * 1024 + t;
    if (i < n) {
        int r = g_rowptr[i] + prefix;
        g_rowptr[i] = r;
        g_cursor[i] = r;
        g_norm[i] = 1.0f / (float)(1 + g_cnt[i]);
    }
    if (blockIdx.x == gridDim.x - 1 && t == 0) g_rowptr[n] = sht[0];
}

// ---------------- CSR scatter (4 edges/thread) ----------------
__global__ void scatter_kernel(const int* __restrict__ src,
                               const int* __restrict__ dst, int e) {
    int i0 = (blockIdx.x * blockDim.x + threadIdx.x) * 4;
    if (i0 >= e) return;
    if (i0 + 4 <= e) {
        int4 s4 = *(const int4*)(src + i0);
        int4 d4 = *(const int4*)(dst + i0);
        int p0 = atomicAdd(&g_cursor[d4.x], 1); g_col[p0] = s4.x;
        int p1 = atomicAdd(&g_cursor[d4.y], 1); g_col[p1] = s4.y;
        int p2 = atomicAdd(&g_cursor[d4.z], 1); g_col[p2] = s4.z;
        int p3 = atomicAdd(&g_cursor[d4.w], 1); g_col[p3] = s4.w;
    } else {
        for (int i = i0; i < e; i++) {
            int p = atomicAdd(&g_cursor[dst[i]], 1);
            g_col[p] = src[i];
        }
    }
}

// ---------------- dense linear: out[n,64] = x[n,K] @ W[K,64] + b ----------------
template <int K>
__global__ __launch_bounds__(256) void lin_kernel(const float* __restrict__ x,
                                                  const float* __restrict__ W,
                                                  const float* __restrict__ b,
                                                  float* __restrict__ out, int n) {
    __shared__ float Ws[K * HID];
    __shared__ float bs[HID];
    for (int i = threadIdx.x; i < (K * HID) / 4; i += blockDim.x)
        ((float4*)Ws)[i] = ((const float4*)W)[i];
    if (threadIdx.x < HID) bs[threadIdx.x] = b[threadIdx.x];
    __syncthreads();

    int row = blockIdx.x * blockDim.x + threadIdx.x;
    if (row >= n) return;

    float acc[HID];
#pragma unroll
    for (int c = 0; c < HID; c++) acc[c] = 0.f;

    const float4* xr = (const float4*)(x + (size_t)row * K);
#pragma unroll
    for (int k4 = 0; k4 < K / 4; k4++) {
        float4 xv = xr[k4];
        float xk[4] = {xv.x, xv.y, xv.z, xv.w};
#pragma unroll
        for (int kk = 0; kk < 4; kk++) {
            float xs = xk[kk];
            const float4* wr = (const float4*)(Ws + (k4 * 4 + kk) * HID);
#pragma unroll
            for (int c = 0; c < HID / 4; c++) {
                float4 w = wr[c];
                acc[4 * c + 0] += xs * w.x;
                acc[4 * c + 1] += xs * w.y;
                acc[4 * c + 2] += xs * w.z;
                acc[4 * c + 3] += xs * w.w;
            }
        }
    }

    float4* o = (float4*)(out + (size_t)row * HID);
#pragma unroll
    for (int c = 0; c < HID / 4; c++) {
        float4 v;
        v.x = acc[4 * c + 0] + bs[4 * c + 0];
        v.y = acc[4 * c + 1] + bs[4 * c + 1];
        v.z = acc[4 * c + 2] + bs[4 * c + 2];
        v.w = acc[4 * c + 3] + bs[4 * c + 3];
        o[c] = v;
    }
}

// ---------------- layer-1 aggregation + combine + relu: warp per node ----------------
__global__ void agg_kernel(const float* __restrict__ h,
                           const float* __restrict__ wpan,
                           float* __restrict__ out, int n) {
    int wid = (blockIdx.x * blockDim.x + threadIdx.x) >> 5;
    int lane = threadIdx.x & 31;
    if (wid >= n) return;
    int lo = g_rowptr[wid], hi = g_rowptr[wid + 1];
    const float2* h2 = (const float2*)h;
    float ax = 0.f, ay = 0.f;
    int j = lo;
    for (; j + 1 < hi; j += 2) {
        int s0 = g_col[j];
        int s1 = g_col[j + 1];
        float2 v0 = h2[(size_t)s0 * 32 + lane];
        float2 v1 = h2[(size_t)s1 * 32 + lane];
        ax += v0.x; ay += v0.y;
        ax += v1.x; ay += v1.y;
    }
    if (j < hi) {
        float2 v0 = h2[(size_t)g_col[j] * 32 + lane];
        ax += v0.x; ay += v0.y;
    }
    float w0 = wpan[0];
    float w01 = w0 * wpan[1];
    float nm = g_norm[wid];
    float2 hv = h2[(size_t)wid * 32 + lane];
    float ox = fmaxf(nm * (w0 * hv.x + w01 * ax), 0.f);
    float oy = fmaxf(nm * (w0 * hv.y + w01 * ay), 0.f);
    ((float2*)out)[(size_t)wid * 32 + lane] = make_float2(ox, oy);
}

// ---------------- FUSED layer-2 aggregation + classifier halves ----------------
// computes final h row in-warp, then pq[i] = (h@wc_top, h@wc_bot) via warp reduce.
// never materializes the layer-2 output.
__global__ void agg2pq_kernel(const float* __restrict__ h,
                              const float* __restrict__ wpan,
                              const float* __restrict__ wc, int n) {
    int wid = (blockIdx.x * blockDim.x + threadIdx.x) >> 5;
    int lane = threadIdx.x & 31;
    if (wid >= n) return;
    int lo = g_rowptr[wid], hi = g_rowptr[wid + 1];
    const float2* h2 = (const float2*)h;
    float ax = 0.f, ay = 0.f;
    int j = lo;
    for (; j + 1 < hi; j += 2) {
        int s0 = g_col[j];
        int s1 = g_col[j + 1];
        float2 v0 = h2[(size_t)s0 * 32 + lane];
        float2 v1 = h2[(size_t)s1 * 32 + lane];
        ax += v0.x; ay += v0.y;
        ax += v1.x; ay += v1.y;
    }
    if (j < hi) {
        float2 v0 = h2[(size_t)g_col[j] * 32 + lane];
        ax += v0.x; ay += v0.y;
    }
    float w0 = wpan[0];
    float w01 = w0 * wpan[1];
    float nm = g_norm[wid];
    float2 hv = h2[(size_t)wid * 32 + lane];
    float ox = nm * (w0 * hv.x + w01 * ax);   // h_final[2*lane]
    float oy = nm * (w0 * hv.y + w01 * ay);   // h_final[2*lane+1]

    // classifier halves: wc is [128,2] row-major; rows 0..63 = src half, 64..127 = dst half
    int c0 = 2 * lane, c1 = 2 * lane + 1;
    float p0 = ox * __ldg(&wc[c0 * 2 + 0]) + oy * __ldg(&wc[c1 * 2 + 0]);
    float p1 = ox * __ldg(&wc[c0 * 2 + 1]) + oy * __ldg(&wc[c1 * 2 + 1]);
    float q0 = ox * __ldg(&wc[(64 + c0) * 2 + 0]) + oy * __ldg(&wc[(64 + c1) * 2 + 0]);
    float q1 = ox * __ldg(&wc[(64 + c0) * 2 + 1]) + oy * __ldg(&wc[(64 + c1) * 2 + 1]);
#pragma unroll
    for (int off = 16; off > 0; off >>= 1) {
        p0 += __shfl_down_sync(0xffffffffu, p0, off);
        p1 += __shfl_down_sync(0xffffffffu, p1, off);
        q0 += __shfl_down_sync(0xffffffffu, q0, off);
        q1 += __shfl_down_sync(0xffffffffu, q1, off);
    }
    if (lane == 0) g_pq[wid] = make_float4(p0, p1, q0, q1);
}

// ---------------- per-edge output (4 edges/thread) ----------------
__global__ void edge_kernel(const int* __restrict__ src,
                            const int* __restrict__ dst,
                            const float* __restrict__ bc,
                            float* __restrict__ out, int e) {
    int i0 = (blockIdx.x * blockDim.x + threadIdx.x) * 4;
    if (i0 >= e) return;
    float b0 = __ldg(&bc[0]), b1 = __ldg(&bc[1]);
    if (i0 + 4 <= e) {
        int4 s4 = *(const int4*)(src + i0);
        int4 d4 = *(const int4*)(dst + i0);
        float4 pa = g_pq[s4.x], qa = g_pq[d4.x];
        float4 pb = g_pq[s4.y], qb = g_pq[d4.y];
        float4 pc = g_pq[s4.z], qc = g_pq[d4.z];
        float4 pd = g_pq[s4.w], qd = g_pq[d4.w];
        float4 o0, o1;
        o0.x = pa.x + qa.z + b0; o0.y = pa.y + qa.w + b1;
        o0.z = pb.x + qb.z + b0; o0.w = pb.y + qb.w + b1;
        o1.x = pc.x + qc.z + b0; o1.y = pc.y + qc.w + b1;
        o1.z = pd.x + qd.z + b0; o1.w = pd.y + qd.w + b1;
        ((float4*)(out + (size_t)i0 * 2))[0] = o0;
        ((float4*)(out + (size_t)i0 * 2))[1] = o1;
    } else {
        for (int i = i0; i < e; i++) {
            float4 ps = g_pq[src[i]];
            float4 qd = g_pq[dst[i]];
            ((float2*)out)[i] = make_float2(ps.x + qd.z + b0, ps.y + qd.w + b1);
        }
    }
}

// ---------------- launch ----------------
extern "C" void kernel_launch(void* const* d_in, const int* in_sizes, int n_in,
                              void* d_out, int out_size) {
    const float* x   = (const float*)d_in[0];
    const int*   ei  = (const int*)d_in[1];
    const float* w1  = (const float*)d_in[2];
    const float* b1  = (const float*)d_in[3];
    const float* p1  = (const float*)d_in[4];  // w1_pan
    const float* w2  = (const float*)d_in[5];
    const float* b2  = (const float*)d_in[6];
    const float* p2  = (const float*)d_in[7];  // w2_pan
    const float* wc  = (const float*)d_in[8];
    const float* bc  = (const float*)d_in[9];
    float* out = (float*)d_out;

    int n = in_sizes[0] / 128;
    int e = in_sizes[1] / 2;
    const int* src = ei;
    const int* dst = ei + e;

    float* bufA = nullptr;
    float* bufB = nullptr;
    cudaGetSymbolAddress((void**)&bufA, g_bufA);
    cudaGetSymbolAddress((void**)&bufB, g_bufB);

    int nb256 = (n + 255) / 256;
    int nb1024 = (n + 1023) / 1024;
    int ebv = (e / 4 + 255) / 256 + 1;        // 4 edges/thread blocks (covers tail)
    int nbLin = (2 * n + 255) / 256;          // half-row lin1 blocks

    init_kernel<<<2048, 256>>>(n);
    fused_lin1_hist_kernel<<<nbLin + ebv, 256>>>(x, w1, b1, src, dst, bufA, n, e, nbLin);
    scan1_kernel<<<nb1024, 1024>>>(n);
    scan3_kernel<<<nb1024, 1024>>>(n, nb1024);
    scatter_kernel<<<ebv, 256>>>(src, dst, e);

    agg_kernel<<<(n * 32 + 255) / 256, 256>>>(bufA, p1, bufB, n);      // layer-1 agg + relu
    lin_kernel<64><<<nb256, 256>>>(bufB, w2, b2, bufA, n);             // layer-2 lin
    agg2pq_kernel<<<(n * 32 + 255) / 256, 256>>>(bufA, p2, wc, n);     // layer-2 agg + pq
    edge_kernel<<<ebv, 256>>>(src, dst, bc, out, e);
}